// round 12
// baseline (speedup 1.0000x reference)
#include <cuda_runtime.h>
#include <cuda_fp16.h>
#include <math.h>
#include <stdint.h>

#define Bb   8
#define Nn   128
#define Cc   256
#define HIDD 1024
#define ROWS_Y (Bb*Nn*Nn)   /* 131072 */
#define ROWS_X (Bb*Nn)      /* 1024   */
#define QR    (ROWS_Y/4)    /* 32768 rows per mlp2 quarter */

// ---------------- fp32 scratch ---------------------------------------------
__device__ float g_x1[ROWS_X*Cc];
__device__ float g_q [ROWS_X*Cc];
__device__ float g_k [ROWS_X*Cc];
__device__ float g_v [ROWS_X*Cc];
__device__ float g_x2pre[ROWS_X*Cc];
__device__ float g_x2  [ROWS_X*Cc];
__device__ float g_oxpre[ROWS_X*Cc];

// ---------------- fp16 scratch ---------------------------------------------
__device__ __half g_yh   [(size_t)ROWS_Y*Cc];   // 67 MB
__device__ __half g_attnh[(size_t)ROWS_Y*Cc];   // 67 MB
__device__ __half g_y2h  [(size_t)ROWS_Y*Cc];   // 67 MB
__device__ __half g_hidQ [(size_t)QR*HIDD];     // 67 MB, reused x4 (L2-resident)
__device__ __half g_x1h [ROWS_X*Cc];
__device__ __half g_aggh[ROWS_X*Cc];
__device__ __half g_x2h [ROWS_X*Cc];
__device__ __half g_hidXh[(size_t)ROWS_X*HIDD];
__device__ __half g_Wh[6][Cc*Cc];               // q,k,v,e,oe,on
__device__ __half g_M1w1h[Cc*HIDD];
__device__ __half g_M1w2h[HIDD*Cc];
__device__ __half g_M2w1h[Cc*HIDD];
__device__ __half g_M2w2h[HIDD*Cc];

// ---------------- helpers --------------------------------------------------
__device__ __forceinline__ uint32_t smem_u32(const void* p) {
    uint32_t a;
    asm("{ .reg .u64 t; cvta.to.shared.u64 t, %1; cvt.u32.u64 %0, t; }" : "=r"(a) : "l"(p));
    return a;
}
__device__ __forceinline__ void cp16(uint32_t dst, const void* src) {
    asm volatile("cp.async.ca.shared.global [%0], [%1], 16;" :: "r"(dst), "l"(src));
}
#define LDMX4(r0,r1,r2,r3,addr) \
    asm volatile("ldmatrix.sync.aligned.m8n8.x4.shared.b16 {%0,%1,%2,%3}, [%4];" \
        : "=r"(r0),"=r"(r1),"=r"(r2),"=r"(r3) : "r"(addr))
#define LDMX4T(r0,r1,r2,r3,addr) \
    asm volatile("ldmatrix.sync.aligned.m8n8.x4.trans.shared.b16 {%0,%1,%2,%3}, [%4];" \
        : "=r"(r0),"=r"(r1),"=r"(r2),"=r"(r3) : "r"(addr))
__device__ __forceinline__ void mma_f16(float d[4], const uint32_t a[4], const uint32_t b[2]) {
    asm volatile(
        "mma.sync.aligned.m16n8k16.row.col.f32.f16.f16.f32 "
        "{%0,%1,%2,%3}, {%4,%5,%6,%7}, {%8,%9}, {%0,%1,%2,%3};"
        : "+f"(d[0]), "+f"(d[1]), "+f"(d[2]), "+f"(d[3])
        : "r"(a[0]), "r"(a[1]), "r"(a[2]), "r"(a[3]), "r"(b[0]), "r"(b[1]));
}

// ======================= BIG kernel: 128x256 tile, 256 thr, 3-stage ========
#define BPAH 40      /* A pitch (halves) */
#define BPBH 264     /* B pitch (halves) */
#define BKC  32
#define A_ST (128 * BPAH)
#define B_ST (BKC * BPBH)
#define BIG_SMEM ((3 * (A_ST + B_ST)) * 2 + 128 * 4 * 2 * 4)

// mode 0: v = acc+bias (+relu) -> outh
// mode 1: attn epilogue -> outh
// mode 2: v = acc+bias+(add|addh), row-LN(256) -> outf (fp32) and/or outh
__global__ void __launch_bounds__(256, 1) gemm_big(
    const __half* __restrict__ A, const __half* __restrict__ Bw,
    const float* __restrict__ bias,
    const float* __restrict__ add, const __half* __restrict__ addh,
    const float* __restrict__ qp, const float* __restrict__ kp,
    const float* __restrict__ lnS, const float* __restrict__ lnB,
    float* __restrict__ outf, __half* __restrict__ outh,
    int N, int K, int relu, int mode, int rowOff)
{
    extern __shared__ __half dsm[];
    __half* As = dsm;
    __half* Bs = dsm + 3 * A_ST;
    float* redS = (float*)(dsm + 3 * (A_ST + B_ST));
    float* redQ = redS + 128 * 4;

    const int tid  = threadIdx.x;
    const int lane = tid & 31;
    const int wid  = tid >> 5;
    const int wm   = (wid & 1) * 64;
    const int wn   = (wid >> 1) * 64;
    const int r    = lane >> 2;
    const int cq   = lane & 3;
    const int l15  = lane & 15;
    const int lhi  = lane >> 4;
    const int m0 = blockIdx.y * 128;
    const int n0 = blockIdx.x * 256;

    const uint32_t sAu = smem_u32(As);
    const uint32_t sBu = smem_u32(Bs);

    float acc[4][8][4];
    #pragma unroll
    for (int i = 0; i < 4; i++)
        #pragma unroll
        for (int j = 0; j < 8; j++)
            #pragma unroll
            for (int t = 0; t < 4; t++) acc[i][j][t] = 0.f;

    const int NC = K / BKC;

    auto load_chunk = [&](int ci, int st) {
        const uint32_t dA = sAu + (uint32_t)(st * A_ST) * 2;
        const uint32_t dB = sBu + (uint32_t)(st * B_ST) * 2;
        const int k0 = ci * BKC;
        #pragma unroll
        for (int j = 0; j < 2; j++) {
            int o = j * 256 + tid;
            int row = o >> 2, seg = o & 3;
            cp16(dA + (uint32_t)(row * BPAH + seg * 8) * 2,
                 A + (size_t)(m0 + row) * K + k0 + seg * 8);
        }
        #pragma unroll
        for (int j = 0; j < 4; j++) {
            int o = j * 256 + tid;
            int kr = o >> 5, seg = o & 31;
            cp16(dB + (uint32_t)(kr * BPBH + seg * 8) * 2,
                 Bw + (size_t)(k0 + kr) * N + n0 + seg * 8);
        }
        asm volatile("cp.async.commit_group;");
    };

    load_chunk(0, 0);
    if (NC > 1) load_chunk(1, 1);

    for (int ci = 0; ci < NC; ci++) {
        const int st = ci % 3;
        asm volatile("cp.async.wait_group 1;");
        __syncthreads();

        const uint32_t aBase = sAu + (uint32_t)(st * A_ST) * 2;
        const uint32_t bBase = sBu + (uint32_t)(st * B_ST) * 2;
        #pragma unroll
        for (int ksub = 0; ksub < 2; ksub++) {
            const int k0s = ksub * 16;
            uint32_t a[4][4];
            uint32_t b[8][2];
            const uint32_t aaddr0 = aBase + (uint32_t)((wm + l15) * BPAH + k0s + 8 * lhi) * 2;
            #pragma unroll
            for (int tm = 0; tm < 4; tm++)
                LDMX4(a[tm][0], a[tm][1], a[tm][2], a[tm][3],
                      aaddr0 + (uint32_t)(tm * 16 * BPAH) * 2);
            const uint32_t baddr0 = bBase + (uint32_t)((k0s + l15) * BPBH + wn + 8 * lhi) * 2;
            #pragma unroll
            for (int tnn = 0; tnn < 4; tnn++)
                LDMX4T(b[2*tnn][0], b[2*tnn][1], b[2*tnn+1][0], b[2*tnn+1][1],
                       baddr0 + (uint32_t)(tnn * 16) * 2);
            #pragma unroll
            for (int tm = 0; tm < 4; tm++)
                #pragma unroll
                for (int tn = 0; tn < 8; tn++)
                    mma_f16(acc[tm][tn], a[tm], b[tn]);
        }
        __syncthreads();
        if (ci + 2 < NC) load_chunk(ci + 2, (ci + 2) % 3);
    }
    asm volatile("cp.async.wait_group 0;");

    // ====================== epilogues ======================
    if (mode == 0) {
        #pragma unroll
        for (int tm = 0; tm < 4; tm++) {
            int r0 = m0 + wm + tm * 16 + r;
            #pragma unroll
            for (int tn = 0; tn < 8; tn++) {
                int cg = n0 + wn + tn * 8 + cq * 2;
                float2 bb = *(const float2*)&bias[cg];
                float v0 = acc[tm][tn][0] + bb.x;
                float v1 = acc[tm][tn][1] + bb.y;
                float v2 = acc[tm][tn][2] + bb.x;
                float v3 = acc[tm][tn][3] + bb.y;
                if (relu) {
                    v0 = fmaxf(v0, 0.f); v1 = fmaxf(v1, 0.f);
                    v2 = fmaxf(v2, 0.f); v3 = fmaxf(v3, 0.f);
                }
                size_t off0 = (size_t)r0 * N + cg;
                size_t off1 = (size_t)(r0 + 8) * N + cg;
                *(__half2*)&outh[off0] = __floats2half2_rn(v0, v1);
                *(__half2*)&outh[off1] = __floats2half2_rn(v2, v3);
            }
        }
    } else if (mode == 1) {
        const float s = 0.17677669529663687f; // 1/sqrt(32)
        #pragma unroll
        for (int tm = 0; tm < 4; tm++) {
            #pragma unroll
            for (int rr2 = 0; rr2 < 2; rr2++) {
                int rrow = m0 + wm + tm * 16 + r + rr2 * 8;
                int jj   = rrow & (Nn - 1);
                int biIx = rrow >> 7;
                int bIx  = biIx >> 7;
                const float* qrow = qp + (size_t)biIx * Cc;
                const float* krow = kp + (size_t)(bIx * Nn + jj) * Cc;
                size_t roff = (size_t)rrow * N;
                #pragma unroll
                for (int tn = 0; tn < 8; tn++) {
                    int cg = wn + tn * 8 + cq * 2;
                    float2 bb = *(const float2*)&bias[cg];
                    float2 qq = *(const float2*)&qrow[cg];
                    float2 kk2 = *(const float2*)&krow[cg];
                    float e0 = acc[tm][tn][rr2 * 2 + 0] + bb.x;
                    float e1 = acc[tm][tn][rr2 * 2 + 1] + bb.y;
                    float a0 = qq.x * kk2.x * s;
                    float a1 = qq.y * kk2.y * s;
                    *(__half2*)&outh[roff + cg] =
                        __floats2half2_rn(a0 * (e0 + 1.f) * e0, a1 * (e1 + 1.f) * e1);
                }
            }
        }
    } else {
        // mode 2: bias + residual (fp32 add or fp16 addh), then row-LN(256)
        #pragma unroll
        for (int tm = 0; tm < 4; tm++) {
            float s0 = 0.f, q0 = 0.f, s1 = 0.f, q1 = 0.f;
            int r0 = m0 + wm + tm * 16 + r;
            #pragma unroll
            for (int tn = 0; tn < 8; tn++) {
                int cg = wn + tn * 8 + cq * 2;
                float2 bb = *(const float2*)&bias[cg];
                size_t off0 = (size_t)r0 * 256 + cg;
                size_t off1 = (size_t)(r0 + 8) * 256 + cg;
                float2 d0, d1;
                if (addh) {
                    d0 = __half22float2(*(const __half2*)&addh[off0]);
                    d1 = __half22float2(*(const __half2*)&addh[off1]);
                } else {
                    d0 = *(const float2*)&add[off0];
                    d1 = *(const float2*)&add[off1];
                }
                float v0 = acc[tm][tn][0] + bb.x + d0.x;
                float v1 = acc[tm][tn][1] + bb.y + d0.y;
                float v2 = acc[tm][tn][2] + bb.x + d1.x;
                float v3 = acc[tm][tn][3] + bb.y + d1.y;
                acc[tm][tn][0] = v0; acc[tm][tn][1] = v1;
                acc[tm][tn][2] = v2; acc[tm][tn][3] = v3;
                s0 += v0 + v1; q0 += v0 * v0 + v1 * v1;
                s1 += v2 + v3; q1 += v2 * v2 + v3 * v3;
            }
            #pragma unroll
            for (int o = 1; o <= 2; o <<= 1) {
                s0 += __shfl_xor_sync(0xffffffffu, s0, o);
                q0 += __shfl_xor_sync(0xffffffffu, q0, o);
                s1 += __shfl_xor_sync(0xffffffffu, s1, o);
                q1 += __shfl_xor_sync(0xffffffffu, q1, o);
            }
            if (cq == 0) {
                int rl0 = wm + tm * 16 + r;
                redS[rl0 * 4 + (wid >> 1)] = s0;
                redQ[rl0 * 4 + (wid >> 1)] = q0;
                redS[(rl0 + 8) * 4 + (wid >> 1)] = s1;
                redQ[(rl0 + 8) * 4 + (wid >> 1)] = q1;
            }
        }
        __syncthreads();
        #pragma unroll
        for (int tm = 0; tm < 4; tm++) {
            #pragma unroll
            for (int rr2 = 0; rr2 < 2; rr2++) {
                int rl = wm + tm * 16 + r + rr2 * 8;
                float ts = redS[rl * 4 + 0] + redS[rl * 4 + 1] + redS[rl * 4 + 2] + redS[rl * 4 + 3];
                float tq = redQ[rl * 4 + 0] + redQ[rl * 4 + 1] + redQ[rl * 4 + 2] + redQ[rl * 4 + 3];
                float mean = ts * (1.f / 256.f);
                float var  = tq * (1.f / 256.f) - mean * mean;
                float inv  = rsqrtf(var + 1e-5f);
                size_t roff = (size_t)(m0 + rl) * 256;
                #pragma unroll
                for (int tn = 0; tn < 8; tn++) {
                    int cg = wn + tn * 8 + cq * 2;
                    float2 ss = *(const float2*)&lnS[cg];
                    float2 bb2 = *(const float2*)&lnB[cg];
                    float v0 = acc[tm][tn][rr2 * 2 + 0];
                    float v1 = acc[tm][tn][rr2 * 2 + 1];
                    float o0 = (v0 - mean) * inv * ss.x + bb2.x;
                    float o1 = (v1 - mean) * inv * ss.y + bb2.y;
                    if (outf)
                        *(float2*)&outf[roff + cg] = make_float2(o0, o1);
                    if (outh)
                        *(__half2*)&outh[roff + cg] = __floats2half2_rn(o0, o1);
                }
            }
        }
    }
    (void)rowOff;
}

// =================== small fp16 GEMM (x-path), 128 thr =====================
#define PAH 40
#define PBH 136
#define KC  32
__global__ void __launch_bounds__(128, 2) gemm_h(
    const __half* __restrict__ A, const __half* __restrict__ Bw,
    const float* __restrict__ bias, const float* __restrict__ add,
    float* __restrict__ outf, __half* __restrict__ outh,
    int N, int K, int relu)
{
    __shared__ __half As[2][128 * PAH];
    __shared__ __half Bs[2][KC * PBH];
    const int tid  = threadIdx.x;
    const int lane = tid & 31;
    const int wid  = tid >> 5;
    const int wm   = (wid & 1) * 64;
    const int wn   = (wid >> 1) * 64;
    const int r    = lane >> 2;
    const int cq   = lane & 3;
    const int l15  = lane & 15;
    const int lhi  = lane >> 4;
    const int m0 = blockIdx.y * 128;
    const int n0 = blockIdx.x * 128;

    const uint32_t sA[2] = { smem_u32(As[0]), smem_u32(As[1]) };
    const uint32_t sB[2] = { smem_u32(Bs[0]), smem_u32(Bs[1]) };

    float acc[4][8][4];
    #pragma unroll
    for (int i = 0; i < 4; i++)
        #pragma unroll
        for (int j = 0; j < 8; j++)
            #pragma unroll
            for (int t = 0; t < 4; t++) acc[i][j][t] = 0.f;

    const int NC = K / KC;
    {
        #pragma unroll
        for (int j = 0; j < 4; j++) {
            int o = j * 128 + tid;
            int row = o >> 2, seg = o & 3;
            cp16(sA[0] + (uint32_t)(row * PAH + seg * 8) * 2,
                 A + (size_t)(m0 + row) * K + seg * 8);
        }
        #pragma unroll
        for (int j = 0; j < 4; j++) {
            int o = j * 128 + tid;
            int kr = o >> 4, seg = o & 15;
            cp16(sB[0] + (uint32_t)(kr * PBH + seg * 8) * 2,
                 Bw + (size_t)kr * N + n0 + seg * 8);
        }
        asm volatile("cp.async.commit_group;");
    }
    for (int ci = 0; ci < NC; ci++) {
        const int buf = ci & 1;
        if (ci + 1 < NC) {
            const uint32_t dA = sA[buf ^ 1];
            const int k0 = (ci + 1) * KC;
            #pragma unroll
            for (int j = 0; j < 4; j++) {
                int o = j * 128 + tid;
                int row = o >> 2, seg = o & 3;
                cp16(dA + (uint32_t)(row * PAH + seg * 8) * 2,
                     A + (size_t)(m0 + row) * K + k0 + seg * 8);
            }
            #pragma unroll
            for (int j = 0; j < 4; j++) {
                int o = j * 128 + tid;
                int kr = o >> 4, seg = o & 15;
                cp16(sB[buf ^ 1] + (uint32_t)(kr * PBH + seg * 8) * 2,
                     Bw + (size_t)(k0 + kr) * N + n0 + seg * 8);
            }
            asm volatile("cp.async.commit_group;");
            asm volatile("cp.async.wait_group 1;");
        } else {
            asm volatile("cp.async.wait_group 0;");
        }
        __syncthreads();
        #pragma unroll
        for (int ksub = 0; ksub < 2; ksub++) {
            const int k0 = ksub * 16;
            uint32_t a[4][4];
            uint32_t b[8][2];
            const uint32_t aaddr0 = sA[buf] + (uint32_t)((wm + l15) * PAH + k0 + 8 * lhi) * 2;
            #pragma unroll
            for (int tm = 0; tm < 4; tm++)
                LDMX4(a[tm][0], a[tm][1], a[tm][2], a[tm][3],
                      aaddr0 + (uint32_t)(tm * 16 * PAH) * 2);
            const uint32_t baddr0 = sB[buf] + (uint32_t)((k0 + l15) * PBH + wn + 8 * lhi) * 2;
            #pragma unroll
            for (int tnn = 0; tnn < 4; tnn++)
                LDMX4T(b[2*tnn][0], b[2*tnn][1], b[2*tnn+1][0], b[2*tnn+1][1],
                       baddr0 + (uint32_t)(tnn * 16) * 2);
            #pragma unroll
            for (int tm = 0; tm < 4; tm++)
                #pragma unroll
                for (int tn = 0; tn < 8; tn++)
                    mma_f16(acc[tm][tn], a[tm], b[tn]);
        }
        __syncthreads();
    }
    #pragma unroll
    for (int tm = 0; tm < 4; tm++) {
        int r0 = m0 + wm + tm * 16 + r;
        #pragma unroll
        for (int tn = 0; tn < 8; tn++) {
            int cg = n0 + wn + tn * 8 + cq * 2;
            float2 bb = *(const float2*)&bias[cg];
            float v0 = acc[tm][tn][0] + bb.x;
            float v1 = acc[tm][tn][1] + bb.y;
            float v2 = acc[tm][tn][2] + bb.x;
            float v3 = acc[tm][tn][3] + bb.y;
            size_t off0 = (size_t)r0 * N + cg;
            size_t off1 = (size_t)(r0 + 8) * N + cg;
            if (add) {
                float2 d0 = *(const float2*)&add[off0];
                float2 d1 = *(const float2*)&add[off1];
                v0 += d0.x; v1 += d0.y; v2 += d1.x; v3 += d1.y;
            }
            if (relu) {
                v0 = fmaxf(v0, 0.f); v1 = fmaxf(v1, 0.f);
                v2 = fmaxf(v2, 0.f); v3 = fmaxf(v3, 0.f);
            }
            if (outh) {
                *(__half2*)&outh[off0] = __floats2half2_rn(v0, v1);
                *(__half2*)&outh[off1] = __floats2half2_rn(v2, v3);
            }
            if (outf) {
                *(float2*)&outf[off0] = make_float2(v0, v1);
                *(float2*)&outf[off1] = make_float2(v2, v3);
            }
        }
    }
}

// ================= fp32 -> fp16 convert (single + batched) =================
__global__ void f2h_kernel(const float* __restrict__ in, __half* __restrict__ out, size_t n)
{
    size_t i = ((size_t)blockIdx.x * blockDim.x + threadIdx.x) * 4;
    if (i < n) {
        float4 v = *(const float4*)(in + i);
        *(__half2*)(out + i)     = __floats2half2_rn(v.x, v.y);
        *(__half2*)(out + i + 2) = __floats2half2_rn(v.z, v.w);
    }
}

struct WBatch {
    const float* src[10];
    __half* dst[10];
    int n[10];
};
__global__ void f2h_batch(WBatch wb)
{
    int a = blockIdx.y;
    const float* in = wb.src[a];
    __half* out = wb.dst[a];
    int n = wb.n[a];
    int i = (blockIdx.x * blockDim.x + threadIdx.x) * 4;
    if (i < n) {
        float4 v = *(const float4*)(in + i);
        *(__half2*)(out + i)     = __floats2half2_rn(v.x, v.y);
        *(__half2*)(out + i + 2) = __floats2half2_rn(v.z, v.w);
    }
}

// ================= row LayerNorm (+ optional fp16 copy) ====================
__global__ void ln_kernel(const float* __restrict__ in,
                          const float* __restrict__ sc,
                          const float* __restrict__ bi,
                          float* __restrict__ out,
                          __half* __restrict__ outh)
{
    int row = blockIdx.x;
    int c   = threadIdx.x;
    size_t idx = (size_t)row * Cc + c;
    float v = in[idx];
    float s = v, q = v * v;
    #pragma unroll
    for (int o = 16; o; o >>= 1) {
        s += __shfl_xor_sync(0xffffffffu, s, o);
        q += __shfl_xor_sync(0xffffffffu, q, o);
    }
    __shared__ float ws[8], wq[8];
    int w = c >> 5, l = c & 31;
    if (l == 0) { ws[w] = s; wq[w] = q; }
    __syncthreads();
    float ts = 0.f, tq = 0.f;
    #pragma unroll
    for (int i = 0; i < 8; i++) { ts += ws[i]; tq += wq[i]; }
    float mean = ts * (1.f / Cc);
    float var  = tq * (1.f / Cc) - mean * mean;
    float inv  = rsqrtf(var + 1e-5f);
    float o = (v - mean) * inv * sc[c] + bi[c];
    out[idx] = o;
    if (outh) outh[idx] = __float2half_rn(o);
}

// ================= softmax over j + aggregate with v (fp16 in) =============
__global__ void softmax_agg_kernel(const __half* __restrict__ attn,
                                   const float* __restrict__ v,
                                   __half* __restrict__ agg)
{
    int bi = blockIdx.x;
    int b  = bi >> 7;
    int c  = threadIdx.x;
    const __half* base = attn + (size_t)bi * Nn * Cc + c;
    const float* vbase = v    + (size_t)b  * Nn * Cc + c;
    float m = -1e30f;
    #pragma unroll 4
    for (int j = 0; j < Nn; j++) m = fmaxf(m, __half2float(base[(size_t)j * Cc]));
    float l = 0.f, acc = 0.f;
    #pragma unroll 4
    for (int j = 0; j < Nn; j++) {
        float p = __expf(__half2float(base[(size_t)j * Cc]) - m);
        l   += p;
        acc += p * vbase[(size_t)j * Cc];
    }
    agg[(size_t)bi * Cc + c] = __float2half_rn(acc / l);
}

// ================= launcher ================================================
extern "C" void kernel_launch(void* const* d_in, const int* in_sizes, int n_in,
                              void* d_out, int out_size)
{
    const float* x    = (const float*)d_in[0];
    const float* y    = (const float*)d_in[1];
    const float* Wq   = (const float*)d_in[2];  const float* bq  = (const float*)d_in[3];
    const float* Wk   = (const float*)d_in[4];  const float* bk  = (const float*)d_in[5];
    const float* Wv   = (const float*)d_in[6];  const float* bv  = (const float*)d_in[7];
    const float* We   = (const float*)d_in[8];  const float* be  = (const float*)d_in[9];
    const float* Woe  = (const float*)d_in[10]; const float* boe = (const float*)d_in[11];
    const float* Won  = (const float*)d_in[12]; const float* bon = (const float*)d_in[13];
    const float* m1w1 = (const float*)d_in[14]; const float* m1b1= (const float*)d_in[15];
    const float* m1w2 = (const float*)d_in[16]; const float* m1b2= (const float*)d_in[17];
    const float* m2w1 = (const float*)d_in[18]; const float* m2b1= (const float*)d_in[19];
    const float* m2w2 = (const float*)d_in[20]; const float* m2b2= (const float*)d_in[21];
    const float* ln1s = (const float*)d_in[22]; const float* ln1b= (const float*)d_in[23];
    const float* ln3s = (const float*)d_in[24]; const float* ln3b= (const float*)d_in[25];
    const float* ln4s = (const float*)d_in[26]; const float* ln4b= (const float*)d_in[27];
    const float* ln5s = (const float*)d_in[28]; const float* ln5b= (const float*)d_in[29];
    const float* ln6s = (const float*)d_in[30]; const float* ln6b= (const float*)d_in[31];

    float *x1, *q, *k, *v, *x2pre, *x2, *oxpre;
    __half *yh, *attnh, *y2h, *hidQ, *x1h, *aggh, *x2h, *hidXh;
    __half *Wh0, *M1w1h, *M1w2h, *M2w1h, *M2w2h;
    cudaGetSymbolAddress((void**)&x1,    g_x1);
    cudaGetSymbolAddress((void**)&q,     g_q);
    cudaGetSymbolAddress((void**)&k,     g_k);
    cudaGetSymbolAddress((void**)&v,     g_v);
    cudaGetSymbolAddress((void**)&x2pre, g_x2pre);
    cudaGetSymbolAddress((void**)&x2,    g_x2);
    cudaGetSymbolAddress((void**)&oxpre, g_oxpre);
    cudaGetSymbolAddress((void**)&yh,    g_yh);
    cudaGetSymbolAddress((void**)&attnh, g_attnh);
    cudaGetSymbolAddress((void**)&y2h,   g_y2h);
    cudaGetSymbolAddress((void**)&hidQ,  g_hidQ);
    cudaGetSymbolAddress((void**)&x1h,   g_x1h);
    cudaGetSymbolAddress((void**)&aggh,  g_aggh);
    cudaGetSymbolAddress((void**)&x2h,   g_x2h);
    cudaGetSymbolAddress((void**)&hidXh, g_hidXh);
    cudaGetSymbolAddress((void**)&Wh0,   g_Wh);
    cudaGetSymbolAddress((void**)&M1w1h, g_M1w1h);
    cudaGetSymbolAddress((void**)&M1w2h, g_M1w2h);
    cudaGetSymbolAddress((void**)&M2w1h, g_M2w1h);
    cudaGetSymbolAddress((void**)&M2w2h, g_M2w2h);
    __half* Wqh  = Wh0 + 0 * Cc * Cc;
    __half* Wkh  = Wh0 + 1 * Cc * Cc;
    __half* Wvh  = Wh0 + 2 * Cc * Cc;
    __half* Weh  = Wh0 + 3 * Cc * Cc;
    __half* Woeh = Wh0 + 4 * Cc * Cc;
    __half* Wonh = Wh0 + 5 * Cc * Cc;

    float* outx = (float*)d_out;
    float* outy = outx + (size_t)ROWS_X * Cc;

    cudaFuncSetAttribute(gemm_big, cudaFuncAttributeMaxDynamicSharedMemorySize, BIG_SMEM);

    // ---- converts: y (big, own kernel) + 10 weights (one batched launch) --
    f2h_kernel<<<(unsigned)(((size_t)ROWS_Y * Cc / 4 + 255) / 256), 256>>>(
        y, yh, (size_t)ROWS_Y * Cc);
    {
        WBatch wb;
        const float* s[10] = {Wq, Wk, Wv, We, Woe, Won, m1w1, m1w2, m2w1, m2w2};
        __half* d[10] = {Wqh, Wkh, Wvh, Weh, Woeh, Wonh, M1w1h, M1w2h, M2w1h, M2w2h};
        int n[10] = {Cc*Cc, Cc*Cc, Cc*Cc, Cc*Cc, Cc*Cc, Cc*Cc,
                     Cc*HIDD, HIDD*Cc, Cc*HIDD, HIDD*Cc};
        for (int i = 0; i < 10; i++) { wb.src[i] = s[i]; wb.dst[i] = d[i]; wb.n[i] = n[i]; }
        f2h_batch<<<dim3((Cc * HIDD / 4 + 255) / 256, 10), 256>>>(wb);
    }

    // x1 = ln1(x)   (fp32 + fp16)
    ln_kernel<<<ROWS_X, 256>>>(x, ln1s, ln1b, x1, x1h);
    // q,k,v (fp32 outputs)
    gemm_h<<<dim3(2, 8), 128>>>(x1h, Wqh, bq, nullptr, q, nullptr, Cc, Cc, 0);
    gemm_h<<<dim3(2, 8), 128>>>(x1h, Wkh, bk, nullptr, k, nullptr, Cc, Cc, 0);
    gemm_h<<<dim3(2, 8), 128>>>(x1h, Wvh, bv, nullptr, v, nullptr, Cc, Cc, 0);
    // attn = (q_i*k_j/sqrt(dk)) * (e+1)*e  -> fp16
    gemm_big<<<dim3(1, 1024), 256, BIG_SMEM>>>(yh, Weh, be, nullptr, nullptr, q, k,
        nullptr, nullptr, nullptr, attnh, Cc, Cc, 0, 1, 0);
    // y2h = ln4(attn@Woe + boe + y)  (fused LN, residual from fp16 yh)
    gemm_big<<<dim3(1, 1024), 256, BIG_SMEM>>>(attnh, Woeh, boe, nullptr, yh, nullptr, nullptr,
        ln4s, ln4b, nullptr, y2h, Cc, Cc, 0, 2, 0);
    // node path: softmax over j, aggregate v -> fp16 agg
    softmax_agg_kernel<<<ROWS_X, 256>>>(attnh, v, aggh);
    gemm_h<<<dim3(2, 8), 128>>>(aggh, Wonh, bon, x1, x2pre, nullptr, Cc, Cc, 0);
    ln_kernel<<<ROWS_X, 256>>>(x2pre, ln3s, ln3b, x2, x2h);
    // x_out = ln5(x2 + mlp1(x2))
    gemm_h<<<dim3(8, 8), 128>>>(x2h, M1w1h, m1b1, nullptr, nullptr, hidXh, HIDD, Cc, 1);
    gemm_h<<<dim3(2, 8), 128>>>(hidXh, M1w2h, m1b2, x2, oxpre, nullptr, Cc, HIDD, 0);
    ln_kernel<<<ROWS_X, 256>>>(oxpre, ln5s, ln5b, outx, nullptr);
    // y_out = ln6(y2 + mlp2(y2)) — 4 quarter-pairs, single reused 67MB hidden
    // buffer keeps the hidden tensor L2-resident between up and down.
    for (int qt = 0; qt < 4; qt++) {
        const __half* y2q = y2h + (size_t)qt * QR * Cc;
        float* outq = outy + (size_t)qt * QR * Cc;
        gemm_big<<<dim3(4, QR / 128), 256, BIG_SMEM>>>(y2q, M2w1h, m2b1,
            nullptr, nullptr, nullptr, nullptr, nullptr, nullptr,
            nullptr, hidQ, HIDD, Cc, 1, 0, 0);
        gemm_big<<<dim3(1, QR / 128), 256, BIG_SMEM>>>(hidQ, M2w2h, m2b2,
            nullptr, y2q, nullptr, nullptr, ln6s, ln6b,
            outq, nullptr, Cc, HIDD, 0, 2, 0);
    }
}

// round 14
// speedup vs baseline: 1.0533x; 1.0533x over previous
#include <cuda_runtime.h>
#include <cuda_fp16.h>
#include <math.h>
#include <stdint.h>

#define Bb   8
#define Nn   128
#define Cc   256
#define HIDD 1024
#define ROWS_Y (Bb*Nn*Nn)   /* 131072 */
#define ROWS_X (Bb*Nn)      /* 1024   */

// ---------------- fp32 scratch ---------------------------------------------
__device__ float g_x1[ROWS_X*Cc];
__device__ float g_q [ROWS_X*Cc];
__device__ float g_k [ROWS_X*Cc];
__device__ float g_v [ROWS_X*Cc];
__device__ float g_x2pre[ROWS_X*Cc];
__device__ float g_x2  [ROWS_X*Cc];
__device__ float g_oxpre[ROWS_X*Cc];

// ---------------- fp16 scratch ---------------------------------------------
__device__ __half g_yh   [(size_t)ROWS_Y*Cc];   // 67 MB
__device__ __half g_attnh[(size_t)ROWS_Y*Cc];   // 67 MB
__device__ __half g_y2h  [(size_t)ROWS_Y*Cc];   // 67 MB
__device__ __half g_hidYh[(size_t)ROWS_Y*HIDD]; // 268 MB
__device__ __half g_x1h [ROWS_X*Cc];
__device__ __half g_aggh[ROWS_X*Cc];
__device__ __half g_x2h [ROWS_X*Cc];
__device__ __half g_hidXh[(size_t)ROWS_X*HIDD];
__device__ __half g_Wh[6][Cc*Cc];               // q,k,v,e,oe,on
__device__ __half g_M1w1h[Cc*HIDD];
__device__ __half g_M1w2h[HIDD*Cc];
__device__ __half g_M2w1h[Cc*HIDD];
__device__ __half g_M2w2h[HIDD*Cc];

// ---------------- helpers --------------------------------------------------
__device__ __forceinline__ uint32_t smem_u32(const void* p) {
    uint32_t a;
    asm("{ .reg .u64 t; cvta.to.shared.u64 t, %1; cvt.u32.u64 %0, t; }" : "=r"(a) : "l"(p));
    return a;
}
__device__ __forceinline__ void cp16(uint32_t dst, const void* src) {
    asm volatile("cp.async.ca.shared.global [%0], [%1], 16;" :: "r"(dst), "l"(src));
}
#define LDMX4(r0,r1,r2,r3,addr) \
    asm volatile("ldmatrix.sync.aligned.m8n8.x4.shared.b16 {%0,%1,%2,%3}, [%4];" \
        : "=r"(r0),"=r"(r1),"=r"(r2),"=r"(r3) : "r"(addr))
#define LDMX4T(r0,r1,r2,r3,addr) \
    asm volatile("ldmatrix.sync.aligned.m8n8.x4.trans.shared.b16 {%0,%1,%2,%3}, [%4];" \
        : "=r"(r0),"=r"(r1),"=r"(r2),"=r"(r3) : "r"(addr))
__device__ __forceinline__ void mma_f16(float d[4], const uint32_t a[4], const uint32_t b[2]) {
    asm volatile(
        "mma.sync.aligned.m16n8k16.row.col.f32.f16.f16.f32 "
        "{%0,%1,%2,%3}, {%4,%5,%6,%7}, {%8,%9}, {%0,%1,%2,%3};"
        : "+f"(d[0]), "+f"(d[1]), "+f"(d[2]), "+f"(d[3])
        : "r"(a[0]), "r"(a[1]), "r"(a[2]), "r"(a[3]), "r"(b[0]), "r"(b[1]));
}

// ======================= BIG kernel: 128x256 tile, 256 thr, 3-stage ========
#define BPAH 40      /* A pitch (halves) */
#define BPBH 264     /* B pitch (halves) */
#define BKC  32
#define A_ST (128 * BPAH)
#define B_ST (BKC * BPBH)
#define BIG_SMEM ((3 * (A_ST + B_ST)) * 2 + 128 * 4 * 2 * 4)

// mode 0: v = acc+bias (+relu) -> outh
// mode 1: attn epilogue -> outh
// mode 2: v = acc+bias+(add|addh), row-LN(256) -> outf (fp32) and/or outh
__global__ void __launch_bounds__(256, 1) gemm_big(
    const __half* __restrict__ A, const __half* __restrict__ Bw,
    const float* __restrict__ bias,
    const float* __restrict__ add, const __half* __restrict__ addh,
    const float* __restrict__ qp, const float* __restrict__ kp,
    const float* __restrict__ lnS, const float* __restrict__ lnB,
    float* __restrict__ outf, __half* __restrict__ outh,
    int N, int K, int relu, int mode)
{
    extern __shared__ __half dsm[];
    __half* As = dsm;
    __half* Bs = dsm + 3 * A_ST;
    float* redS = (float*)(dsm + 3 * (A_ST + B_ST));
    float* redQ = redS + 128 * 4;

    const int tid  = threadIdx.x;
    const int lane = tid & 31;
    const int wid  = tid >> 5;
    const int wm   = (wid & 1) * 64;
    const int wn   = (wid >> 1) * 64;
    const int r    = lane >> 2;
    const int cq   = lane & 3;
    const int l15  = lane & 15;
    const int lhi  = lane >> 4;
    const int m0 = blockIdx.y * 128;
    const int n0 = blockIdx.x * 256;

    const uint32_t sAu = smem_u32(As);
    const uint32_t sBu = smem_u32(Bs);

    float acc[4][8][4];
    #pragma unroll
    for (int i = 0; i < 4; i++)
        #pragma unroll
        for (int j = 0; j < 8; j++)
            #pragma unroll
            for (int t = 0; t < 4; t++) acc[i][j][t] = 0.f;

    const int NC = K / BKC;

    auto load_chunk = [&](int ci, int st) {
        const uint32_t dA = sAu + (uint32_t)(st * A_ST) * 2;
        const uint32_t dB = sBu + (uint32_t)(st * B_ST) * 2;
        const int k0 = ci * BKC;
        #pragma unroll
        for (int j = 0; j < 2; j++) {
            int o = j * 256 + tid;
            int row = o >> 2, seg = o & 3;
            cp16(dA + (uint32_t)(row * BPAH + seg * 8) * 2,
                 A + (size_t)(m0 + row) * K + k0 + seg * 8);
        }
        #pragma unroll
        for (int j = 0; j < 4; j++) {
            int o = j * 256 + tid;
            int kr = o >> 5, seg = o & 31;
            cp16(dB + (uint32_t)(kr * BPBH + seg * 8) * 2,
                 Bw + (size_t)(k0 + kr) * N + n0 + seg * 8);
        }
        asm volatile("cp.async.commit_group;");
    };

    load_chunk(0, 0);
    if (NC > 1) load_chunk(1, 1);

    for (int ci = 0; ci < NC; ci++) {
        const int st = ci % 3;
        asm volatile("cp.async.wait_group 1;");
        __syncthreads();

        const uint32_t aBase = sAu + (uint32_t)(st * A_ST) * 2;
        const uint32_t bBase = sBu + (uint32_t)(st * B_ST) * 2;
        #pragma unroll
        for (int ksub = 0; ksub < 2; ksub++) {
            const int k0s = ksub * 16;
            uint32_t a[4][4];
            uint32_t b[8][2];
            const uint32_t aaddr0 = aBase + (uint32_t)((wm + l15) * BPAH + k0s + 8 * lhi) * 2;
            #pragma unroll
            for (int tm = 0; tm < 4; tm++)
                LDMX4(a[tm][0], a[tm][1], a[tm][2], a[tm][3],
                      aaddr0 + (uint32_t)(tm * 16 * BPAH) * 2);
            const uint32_t baddr0 = bBase + (uint32_t)((k0s + l15) * BPBH + wn + 8 * lhi) * 2;
            #pragma unroll
            for (int tnn = 0; tnn < 4; tnn++)
                LDMX4T(b[2*tnn][0], b[2*tnn][1], b[2*tnn+1][0], b[2*tnn+1][1],
                       baddr0 + (uint32_t)(tnn * 16) * 2);
            #pragma unroll
            for (int tm = 0; tm < 4; tm++)
                #pragma unroll
                for (int tn = 0; tn < 8; tn++)
                    mma_f16(acc[tm][tn], a[tm], b[tn]);
        }
        __syncthreads();
        if (ci + 2 < NC) load_chunk(ci + 2, (ci + 2) % 3);
    }
    asm volatile("cp.async.wait_group 0;");

    // ====================== epilogues ======================
    if (mode == 0) {
        #pragma unroll
        for (int tm = 0; tm < 4; tm++) {
            int r0 = m0 + wm + tm * 16 + r;
            #pragma unroll
            for (int tn = 0; tn < 8; tn++) {
                int cg = n0 + wn + tn * 8 + cq * 2;
                float2 bb = *(const float2*)&bias[cg];
                float v0 = acc[tm][tn][0] + bb.x;
                float v1 = acc[tm][tn][1] + bb.y;
                float v2 = acc[tm][tn][2] + bb.x;
                float v3 = acc[tm][tn][3] + bb.y;
                if (relu) {
                    v0 = fmaxf(v0, 0.f); v1 = fmaxf(v1, 0.f);
                    v2 = fmaxf(v2, 0.f); v3 = fmaxf(v3, 0.f);
                }
                size_t off0 = (size_t)r0 * N + cg;
                size_t off1 = (size_t)(r0 + 8) * N + cg;
                *(__half2*)&outh[off0] = __floats2half2_rn(v0, v1);
                *(__half2*)&outh[off1] = __floats2half2_rn(v2, v3);
            }
        }
    } else if (mode == 1) {
        const float s = 0.17677669529663687f; // 1/sqrt(32)
        #pragma unroll
        for (int tm = 0; tm < 4; tm++) {
            #pragma unroll
            for (int rr2 = 0; rr2 < 2; rr2++) {
                int rrow = m0 + wm + tm * 16 + r + rr2 * 8;
                int jj   = rrow & (Nn - 1);
                int biIx = rrow >> 7;
                int bIx  = biIx >> 7;
                const float* qrow = qp + (size_t)biIx * Cc;
                const float* krow = kp + (size_t)(bIx * Nn + jj) * Cc;
                size_t roff = (size_t)rrow * N;
                #pragma unroll
                for (int tn = 0; tn < 8; tn++) {
                    int cg = wn + tn * 8 + cq * 2;
                    float2 bb = *(const float2*)&bias[cg];
                    float2 qq = *(const float2*)&qrow[cg];
                    float2 kk2 = *(const float2*)&krow[cg];
                    float e0 = acc[tm][tn][rr2 * 2 + 0] + bb.x;
                    float e1 = acc[tm][tn][rr2 * 2 + 1] + bb.y;
                    float a0 = qq.x * kk2.x * s;
                    float a1 = qq.y * kk2.y * s;
                    *(__half2*)&outh[roff + cg] =
                        __floats2half2_rn(a0 * (e0 + 1.f) * e0, a1 * (e1 + 1.f) * e1);
                }
            }
        }
    } else {
        // mode 2: bias + residual (fp32 add or fp16 addh), then row-LN(256)
        #pragma unroll
        for (int tm = 0; tm < 4; tm++) {
            float s0 = 0.f, q0 = 0.f, s1 = 0.f, q1 = 0.f;
            int r0 = m0 + wm + tm * 16 + r;
            #pragma unroll
            for (int tn = 0; tn < 8; tn++) {
                int cg = wn + tn * 8 + cq * 2;
                float2 bb = *(const float2*)&bias[cg];
                size_t off0 = (size_t)r0 * 256 + cg;
                size_t off1 = (size_t)(r0 + 8) * 256 + cg;
                float2 d0, d1;
                if (addh) {
                    d0 = __half22float2(*(const __half2*)&addh[off0]);
                    d1 = __half22float2(*(const __half2*)&addh[off1]);
                } else {
                    d0 = *(const float2*)&add[off0];
                    d1 = *(const float2*)&add[off1];
                }
                float v0 = acc[tm][tn][0] + bb.x + d0.x;
                float v1 = acc[tm][tn][1] + bb.y + d0.y;
                float v2 = acc[tm][tn][2] + bb.x + d1.x;
                float v3 = acc[tm][tn][3] + bb.y + d1.y;
                acc[tm][tn][0] = v0; acc[tm][tn][1] = v1;
                acc[tm][tn][2] = v2; acc[tm][tn][3] = v3;
                s0 += v0 + v1; q0 += v0 * v0 + v1 * v1;
                s1 += v2 + v3; q1 += v2 * v2 + v3 * v3;
            }
            #pragma unroll
            for (int o = 1; o <= 2; o <<= 1) {
                s0 += __shfl_xor_sync(0xffffffffu, s0, o);
                q0 += __shfl_xor_sync(0xffffffffu, q0, o);
                s1 += __shfl_xor_sync(0xffffffffu, s1, o);
                q1 += __shfl_xor_sync(0xffffffffu, q1, o);
            }
            if (cq == 0) {
                int rl0 = wm + tm * 16 + r;
                redS[rl0 * 4 + (wid >> 1)] = s0;
                redQ[rl0 * 4 + (wid >> 1)] = q0;
                redS[(rl0 + 8) * 4 + (wid >> 1)] = s1;
                redQ[(rl0 + 8) * 4 + (wid >> 1)] = q1;
            }
        }
        __syncthreads();
        #pragma unroll
        for (int tm = 0; tm < 4; tm++) {
            #pragma unroll
            for (int rr2 = 0; rr2 < 2; rr2++) {
                int rl = wm + tm * 16 + r + rr2 * 8;
                float ts = redS[rl * 4 + 0] + redS[rl * 4 + 1] + redS[rl * 4 + 2] + redS[rl * 4 + 3];
                float tq = redQ[rl * 4 + 0] + redQ[rl * 4 + 1] + redQ[rl * 4 + 2] + redQ[rl * 4 + 3];
                float mean = ts * (1.f / 256.f);
                float var  = tq * (1.f / 256.f) - mean * mean;
                float inv  = rsqrtf(var + 1e-5f);
                size_t roff = (size_t)(m0 + rl) * 256;
                #pragma unroll
                for (int tn = 0; tn < 8; tn++) {
                    int cg = wn + tn * 8 + cq * 2;
                    float2 ss = *(const float2*)&lnS[cg];
                    float2 bb2 = *(const float2*)&lnB[cg];
                    float v0 = acc[tm][tn][rr2 * 2 + 0];
                    float v1 = acc[tm][tn][rr2 * 2 + 1];
                    float o0 = (v0 - mean) * inv * ss.x + bb2.x;
                    float o1 = (v1 - mean) * inv * ss.y + bb2.y;
                    if (outf)
                        *(float2*)&outf[roff + cg] = make_float2(o0, o1);
                    if (outh)
                        *(__half2*)&outh[roff + cg] = __floats2half2_rn(o0, o1);
                }
            }
        }
    }
}

// =================== small fp16 GEMM (x-path), 128 thr =====================
#define PAH 40
#define PBH 136
#define KC  32
__global__ void __launch_bounds__(128, 2) gemm_h(
    const __half* __restrict__ A, const __half* __restrict__ Bw,
    const float* __restrict__ bias, const float* __restrict__ add,
    float* __restrict__ outf, __half* __restrict__ outh,
    int N, int K, int relu)
{
    __shared__ __half As[2][128 * PAH];
    __shared__ __half Bs[2][KC * PBH];
    const int tid  = threadIdx.x;
    const int lane = tid & 31;
    const int wid  = tid >> 5;
    const int wm   = (wid & 1) * 64;
    const int wn   = (wid >> 1) * 64;
    const int r    = lane >> 2;
    const int cq   = lane & 3;
    const int l15  = lane & 15;
    const int lhi  = lane >> 4;
    const int m0 = blockIdx.y * 128;
    const int n0 = blockIdx.x * 128;

    const uint32_t sA[2] = { smem_u32(As[0]), smem_u32(As[1]) };
    const uint32_t sB[2] = { smem_u32(Bs[0]), smem_u32(Bs[1]) };

    float acc[4][8][4];
    #pragma unroll
    for (int i = 0; i < 4; i++)
        #pragma unroll
        for (int j = 0; j < 8; j++)
            #pragma unroll
            for (int t = 0; t < 4; t++) acc[i][j][t] = 0.f;

    const int NC = K / KC;
    {
        #pragma unroll
        for (int j = 0; j < 4; j++) {
            int o = j * 128 + tid;
            int row = o >> 2, seg = o & 3;
            cp16(sA[0] + (uint32_t)(row * PAH + seg * 8) * 2,
                 A + (size_t)(m0 + row) * K + seg * 8);
        }
        #pragma unroll
        for (int j = 0; j < 4; j++) {
            int o = j * 128 + tid;
            int kr = o >> 4, seg = o & 15;
            cp16(sB[0] + (uint32_t)(kr * PBH + seg * 8) * 2,
                 Bw + (size_t)kr * N + n0 + seg * 8);
        }
        asm volatile("cp.async.commit_group;");
    }
    for (int ci = 0; ci < NC; ci++) {
        const int buf = ci & 1;
        if (ci + 1 < NC) {
            const uint32_t dA = sA[buf ^ 1];
            const int k0 = (ci + 1) * KC;
            #pragma unroll
            for (int j = 0; j < 4; j++) {
                int o = j * 128 + tid;
                int row = o >> 2, seg = o & 3;
                cp16(dA + (uint32_t)(row * PAH + seg * 8) * 2,
                     A + (size_t)(m0 + row) * K + k0 + seg * 8);
            }
            #pragma unroll
            for (int j = 0; j < 4; j++) {
                int o = j * 128 + tid;
                int kr = o >> 4, seg = o & 15;
                cp16(sB[buf ^ 1] + (uint32_t)(kr * PBH + seg * 8) * 2,
                     Bw + (size_t)(k0 + kr) * N + n0 + seg * 8);
            }
            asm volatile("cp.async.commit_group;");
            asm volatile("cp.async.wait_group 1;");
        } else {
            asm volatile("cp.async.wait_group 0;");
        }
        __syncthreads();
        #pragma unroll
        for (int ksub = 0; ksub < 2; ksub++) {
            const int k0 = ksub * 16;
            uint32_t a[4][4];
            uint32_t b[8][2];
            const uint32_t aaddr0 = sA[buf] + (uint32_t)((wm + l15) * PAH + k0 + 8 * lhi) * 2;
            #pragma unroll
            for (int tm = 0; tm < 4; tm++)
                LDMX4(a[tm][0], a[tm][1], a[tm][2], a[tm][3],
                      aaddr0 + (uint32_t)(tm * 16 * PAH) * 2);
            const uint32_t baddr0 = sB[buf] + (uint32_t)((k0 + l15) * PBH + wn + 8 * lhi) * 2;
            #pragma unroll
            for (int tnn = 0; tnn < 4; tnn++)
                LDMX4T(b[2*tnn][0], b[2*tnn][1], b[2*tnn+1][0], b[2*tnn+1][1],
                       baddr0 + (uint32_t)(tnn * 16) * 2);
            #pragma unroll
            for (int tm = 0; tm < 4; tm++)
                #pragma unroll
                for (int tn = 0; tn < 8; tn++)
                    mma_f16(acc[tm][tn], a[tm], b[tn]);
        }
        __syncthreads();
    }
    #pragma unroll
    for (int tm = 0; tm < 4; tm++) {
        int r0 = m0 + wm + tm * 16 + r;
        #pragma unroll
        for (int tn = 0; tn < 8; tn++) {
            int cg = n0 + wn + tn * 8 + cq * 2;
            float2 bb = *(const float2*)&bias[cg];
            float v0 = acc[tm][tn][0] + bb.x;
            float v1 = acc[tm][tn][1] + bb.y;
            float v2 = acc[tm][tn][2] + bb.x;
            float v3 = acc[tm][tn][3] + bb.y;
            size_t off0 = (size_t)r0 * N + cg;
            size_t off1 = (size_t)(r0 + 8) * N + cg;
            if (add) {
                float2 d0 = *(const float2*)&add[off0];
                float2 d1 = *(const float2*)&add[off1];
                v0 += d0.x; v1 += d0.y; v2 += d1.x; v3 += d1.y;
            }
            if (relu) {
                v0 = fmaxf(v0, 0.f); v1 = fmaxf(v1, 0.f);
                v2 = fmaxf(v2, 0.f); v3 = fmaxf(v3, 0.f);
            }
            if (outh) {
                *(__half2*)&outh[off0] = __floats2half2_rn(v0, v1);
                *(__half2*)&outh[off1] = __floats2half2_rn(v2, v3);
            }
            if (outf) {
                *(float2*)&outf[off0] = make_float2(v0, v1);
                *(float2*)&outf[off1] = make_float2(v2, v3);
            }
        }
    }
}

// ================= fp32 -> fp16 convert (single + batched) =================
__global__ void f2h_kernel(const float* __restrict__ in, __half* __restrict__ out, size_t n)
{
    size_t i = ((size_t)blockIdx.x * blockDim.x + threadIdx.x) * 4;
    if (i < n) {
        float4 v = *(const float4*)(in + i);
        *(__half2*)(out + i)     = __floats2half2_rn(v.x, v.y);
        *(__half2*)(out + i + 2) = __floats2half2_rn(v.z, v.w);
    }
}

struct WBatch {
    const float* src[10];
    __half* dst[10];
    int n[10];
};
__global__ void f2h_batch(WBatch wb)
{
    int a = blockIdx.y;
    const float* in = wb.src[a];
    __half* out = wb.dst[a];
    int n = wb.n[a];
    int i = (blockIdx.x * blockDim.x + threadIdx.x) * 4;
    if (i < n) {
        float4 v = *(const float4*)(in + i);
        *(__half2*)(out + i)     = __floats2half2_rn(v.x, v.y);
        *(__half2*)(out + i + 2) = __floats2half2_rn(v.z, v.w);
    }
}

// ================= row LayerNorm (+ optional fp16 copy) ====================
__global__ void ln_kernel(const float* __restrict__ in,
                          const float* __restrict__ sc,
                          const float* __restrict__ bi,
                          float* __restrict__ out,
                          __half* __restrict__ outh)
{
    int row = blockIdx.x;
    int c   = threadIdx.x;
    size_t idx = (size_t)row * Cc + c;
    float v = in[idx];
    float s = v, q = v * v;
    #pragma unroll
    for (int o = 16; o; o >>= 1) {
        s += __shfl_xor_sync(0xffffffffu, s, o);
        q += __shfl_xor_sync(0xffffffffu, q, o);
    }
    __shared__ float ws[8], wq[8];
    int w = c >> 5, l = c & 31;
    if (l == 0) { ws[w] = s; wq[w] = q; }
    __syncthreads();
    float ts = 0.f, tq = 0.f;
    #pragma unroll
    for (int i = 0; i < 8; i++) { ts += ws[i]; tq += wq[i]; }
    float mean = ts * (1.f / Cc);
    float var  = tq * (1.f / Cc) - mean * mean;
    float inv  = rsqrtf(var + 1e-5f);
    float o = (v - mean) * inv * sc[c] + bi[c];
    out[idx] = o;
    if (outh) outh[idx] = __float2half_rn(o);
}

// ================= softmax over j + aggregate with v (fp16 in) =============
__global__ void softmax_agg_kernel(const __half* __restrict__ attn,
                                   const float* __restrict__ v,
                                   __half* __restrict__ agg)
{
    int bi = blockIdx.x;
    int b  = bi >> 7;
    int c  = threadIdx.x;
    const __half* base = attn + (size_t)bi * Nn * Cc + c;
    const float* vbase = v    + (size_t)b  * Nn * Cc + c;
    float m = -1e30f;
    #pragma unroll 4
    for (int j = 0; j < Nn; j++) m = fmaxf(m, __half2float(base[(size_t)j * Cc]));
    float l = 0.f, acc = 0.f;
    #pragma unroll 4
    for (int j = 0; j < Nn; j++) {
        float p = __expf(__half2float(base[(size_t)j * Cc]) - m);
        l   += p;
        acc += p * vbase[(size_t)j * Cc];
    }
    agg[(size_t)bi * Cc + c] = __float2half_rn(acc / l);
}

// ================= launcher ================================================
extern "C" void kernel_launch(void* const* d_in, const int* in_sizes, int n_in,
                              void* d_out, int out_size)
{
    const float* x    = (const float*)d_in[0];
    const float* y    = (const float*)d_in[1];
    const float* Wq   = (const float*)d_in[2];  const float* bq  = (const float*)d_in[3];
    const float* Wk   = (const float*)d_in[4];  const float* bk  = (const float*)d_in[5];
    const float* Wv   = (const float*)d_in[6];  const float* bv  = (const float*)d_in[7];
    const float* We   = (const float*)d_in[8];  const float* be  = (const float*)d_in[9];
    const float* Woe  = (const float*)d_in[10]; const float* boe = (const float*)d_in[11];
    const float* Won  = (const float*)d_in[12]; const float* bon = (const float*)d_in[13];
    const float* m1w1 = (const float*)d_in[14]; const float* m1b1= (const float*)d_in[15];
    const float* m1w2 = (const float*)d_in[16]; const float* m1b2= (const float*)d_in[17];
    const float* m2w1 = (const float*)d_in[18]; const float* m2b1= (const float*)d_in[19];
    const float* m2w2 = (const float*)d_in[20]; const float* m2b2= (const float*)d_in[21];
    const float* ln1s = (const float*)d_in[22]; const float* ln1b= (const float*)d_in[23];
    const float* ln3s = (const float*)d_in[24]; const float* ln3b= (const float*)d_in[25];
    const float* ln4s = (const float*)d_in[26]; const float* ln4b= (const float*)d_in[27];
    const float* ln5s = (const float*)d_in[28]; const float* ln5b= (const float*)d_in[29];
    const float* ln6s = (const float*)d_in[30]; const float* ln6b= (const float*)d_in[31];

    float *x1, *q, *k, *v, *x2pre, *x2, *oxpre;
    __half *yh, *attnh, *y2h, *hidYh, *x1h, *aggh, *x2h, *hidXh;
    __half *Wh0, *M1w1h, *M1w2h, *M2w1h, *M2w2h;
    cudaGetSymbolAddress((void**)&x1,    g_x1);
    cudaGetSymbolAddress((void**)&q,     g_q);
    cudaGetSymbolAddress((void**)&k,     g_k);
    cudaGetSymbolAddress((void**)&v,     g_v);
    cudaGetSymbolAddress((void**)&x2pre, g_x2pre);
    cudaGetSymbolAddress((void**)&x2,    g_x2);
    cudaGetSymbolAddress((void**)&oxpre, g_oxpre);
    cudaGetSymbolAddress((void**)&yh,    g_yh);
    cudaGetSymbolAddress((void**)&attnh, g_attnh);
    cudaGetSymbolAddress((void**)&y2h,   g_y2h);
    cudaGetSymbolAddress((void**)&hidYh, g_hidYh);
    cudaGetSymbolAddress((void**)&x1h,   g_x1h);
    cudaGetSymbolAddress((void**)&aggh,  g_aggh);
    cudaGetSymbolAddress((void**)&x2h,   g_x2h);
    cudaGetSymbolAddress((void**)&hidXh, g_hidXh);
    cudaGetSymbolAddress((void**)&Wh0,   g_Wh);
    cudaGetSymbolAddress((void**)&M1w1h, g_M1w1h);
    cudaGetSymbolAddress((void**)&M1w2h, g_M1w2h);
    cudaGetSymbolAddress((void**)&M2w1h, g_M2w1h);
    cudaGetSymbolAddress((void**)&M2w2h, g_M2w2h);
    __half* Wqh  = Wh0 + 0 * Cc * Cc;
    __half* Wkh  = Wh0 + 1 * Cc * Cc;
    __half* Wvh  = Wh0 + 2 * Cc * Cc;
    __half* Weh  = Wh0 + 3 * Cc * Cc;
    __half* Woeh = Wh0 + 4 * Cc * Cc;
    __half* Wonh = Wh0 + 5 * Cc * Cc;

    float* outx = (float*)d_out;
    float* outy = outx + (size_t)ROWS_X * Cc;

    cudaFuncSetAttribute(gemm_big, cudaFuncAttributeMaxDynamicSharedMemorySize, BIG_SMEM);

    // ---- converts: y (big, own kernel) + 10 weights (one batched launch) --
    f2h_kernel<<<(unsigned)(((size_t)ROWS_Y * Cc / 4 + 255) / 256), 256>>>(
        y, yh, (size_t)ROWS_Y * Cc);
    {
        WBatch wb;
        const float* s[10] = {Wq, Wk, Wv, We, Woe, Won, m1w1, m1w2, m2w1, m2w2};
        __half* d[10] = {Wqh, Wkh, Wvh, Weh, Woeh, Wonh, M1w1h, M1w2h, M2w1h, M2w2h};
        int n[10] = {Cc*Cc, Cc*Cc, Cc*Cc, Cc*Cc, Cc*Cc, Cc*Cc,
                     Cc*HIDD, HIDD*Cc, Cc*HIDD, HIDD*Cc};
        for (int i = 0; i < 10; i++) { wb.src[i] = s[i]; wb.dst[i] = d[i]; wb.n[i] = n[i]; }
        f2h_batch<<<dim3((Cc * HIDD / 4 + 255) / 256, 10), 256>>>(wb);
    }

    // x1 = ln1(x)   (fp32 + fp16)
    ln_kernel<<<ROWS_X, 256>>>(x, ln1s, ln1b, x1, x1h);
    // q,k,v (fp32 outputs)
    gemm_h<<<dim3(2, 8), 128>>>(x1h, Wqh, bq, nullptr, q, nullptr, Cc, Cc, 0);
    gemm_h<<<dim3(2, 8), 128>>>(x1h, Wkh, bk, nullptr, k, nullptr, Cc, Cc, 0);
    gemm_h<<<dim3(2, 8), 128>>>(x1h, Wvh, bv, nullptr, v, nullptr, Cc, Cc, 0);
    // attn = (q_i*k_j/sqrt(dk)) * (e+1)*e  -> fp16
    gemm_big<<<dim3(1, 1024), 256, BIG_SMEM>>>(yh, Weh, be, nullptr, nullptr, q, k,
        nullptr, nullptr, nullptr, attnh, Cc, Cc, 0, 1);
    // y2h = ln4(attn@Woe + boe + y)  (fused LN, residual from fp16 yh)
    gemm_big<<<dim3(1, 1024), 256, BIG_SMEM>>>(attnh, Woeh, boe, nullptr, yh, nullptr, nullptr,
        ln4s, ln4b, nullptr, y2h, Cc, Cc, 0, 2);
    // node path: softmax over j, aggregate v -> fp16 agg
    softmax_agg_kernel<<<ROWS_X, 256>>>(attnh, v, aggh);
    gemm_h<<<dim3(2, 8), 128>>>(aggh, Wonh, bon, x1, x2pre, nullptr, Cc, Cc, 0);
    ln_kernel<<<ROWS_X, 256>>>(x2pre, ln3s, ln3b, x2, x2h);
    // x_out = ln5(x2 + mlp1(x2))
    gemm_h<<<dim3(8, 8), 128>>>(x2h, M1w1h, m1b1, nullptr, nullptr, hidXh, HIDD, Cc, 1);
    gemm_h<<<dim3(2, 8), 128>>>(hidXh, M1w2h, m1b2, x2, oxpre, nullptr, Cc, HIDD, 0);
    ln_kernel<<<ROWS_X, 256>>>(oxpre, ln5s, ln5b, outx, nullptr);
    // y_out = ln6(y2 + mlp2(y2))   (fused LN; residual from fp16 y2h)
    gemm_big<<<dim3(4, 1024), 256, BIG_SMEM>>>(y2h, M2w1h, m2b1, nullptr, nullptr, nullptr, nullptr,
        nullptr, nullptr, nullptr, hidYh, HIDD, Cc, 1, 0);
    gemm_big<<<dim3(1, 1024), 256, BIG_SMEM>>>(hidYh, M2w2h, m2b2, nullptr, y2h, nullptr, nullptr,
        ln6s, ln6b, outy, nullptr, Cc, HIDD, 0, 2);
}